// round 2
// baseline (speedup 1.0000x reference)
#include <cuda_runtime.h>
#include <cstdint>

// ---------------------------------------------------------------------------
// Problem constants
// ---------------------------------------------------------------------------
#define BATCH 8
#define IMG   256
#define CCH   16
#define HID   128
#define NPIX  (BATCH * IMG * IMG)          // 524288 pixels
#define STATE_ELEMS (NPIX * CCH)           // 8388608 floats per buffer
#define STEPS 32

// ping-pong state buffers (NHWC), static device memory (no allocation)
__device__ float g_state[2][STATE_ELEMS];

// ---------------------------------------------------------------------------
// Threefry-2x32 (20 rounds) — exact JAX implementation
// ---------------------------------------------------------------------------
static __host__ __device__ __forceinline__ uint32_t tf_rotl(uint32_t v, int r) {
    return (v << r) | (v >> (32 - r));
}

static __host__ __device__ __forceinline__ void threefry2x32(
    uint32_t k0, uint32_t k1, uint32_t x0, uint32_t x1,
    uint32_t& o0, uint32_t& o1)
{
    uint32_t ks2 = k0 ^ k1 ^ 0x1BD11BDAu;
    x0 += k0; x1 += k1;
    // group 1: rotations 13,15,26,6
    x0 += x1; x1 = tf_rotl(x1, 13); x1 ^= x0;
    x0 += x1; x1 = tf_rotl(x1, 15); x1 ^= x0;
    x0 += x1; x1 = tf_rotl(x1, 26); x1 ^= x0;
    x0 += x1; x1 = tf_rotl(x1,  6); x1 ^= x0;
    x0 += k1; x1 += ks2 + 1u;
    // group 2: rotations 17,29,16,24
    x0 += x1; x1 = tf_rotl(x1, 17); x1 ^= x0;
    x0 += x1; x1 = tf_rotl(x1, 29); x1 ^= x0;
    x0 += x1; x1 = tf_rotl(x1, 16); x1 ^= x0;
    x0 += x1; x1 = tf_rotl(x1, 24); x1 ^= x0;
    x0 += ks2; x1 += k0 + 2u;
    // group 3: rotations 13,15,26,6
    x0 += x1; x1 = tf_rotl(x1, 13); x1 ^= x0;
    x0 += x1; x1 = tf_rotl(x1, 15); x1 ^= x0;
    x0 += x1; x1 = tf_rotl(x1, 26); x1 ^= x0;
    x0 += x1; x1 = tf_rotl(x1,  6); x1 ^= x0;
    x0 += k0; x1 += k1 + 3u;
    // group 4: rotations 17,29,16,24
    x0 += x1; x1 = tf_rotl(x1, 17); x1 ^= x0;
    x0 += x1; x1 = tf_rotl(x1, 29); x1 ^= x0;
    x0 += x1; x1 = tf_rotl(x1, 16); x1 ^= x0;
    x0 += x1; x1 = tf_rotl(x1, 24); x1 ^= x0;
    x0 += k1; x1 += ks2 + 4u;
    // group 5: rotations 13,15,26,6
    x0 += x1; x1 = tf_rotl(x1, 13); x1 ^= x0;
    x0 += x1; x1 = tf_rotl(x1, 15); x1 ^= x0;
    x0 += x1; x1 = tf_rotl(x1, 26); x1 ^= x0;
    x0 += x1; x1 = tf_rotl(x1,  6); x1 ^= x0;
    x0 += ks2; x1 += k0 + 5u;
    o0 = x0; o1 = x1;
}

// ---------------------------------------------------------------------------
// Pack: NCHW input -> NHWC state buffer 0
// ---------------------------------------------------------------------------
__global__ void nca_pack_kernel(const float* __restrict__ x)
{
    int p = blockIdx.x * 256 + threadIdx.x;   // pixel index (b,h,w)
    if (p >= NPIX) return;
    int b  = p >> 16;
    int hw = p & 65535;
    float v[CCH];
#pragma unroll
    for (int c = 0; c < CCH; ++c)
        v[c] = x[((size_t)(b * CCH + c) << 16) + hw];   // coalesced per c
    float4* dst = reinterpret_cast<float4*>(g_state[0] + ((size_t)p << 4));
    dst[0] = make_float4(v[0],  v[1],  v[2],  v[3]);
    dst[1] = make_float4(v[4],  v[5],  v[6],  v[7]);
    dst[2] = make_float4(v[8],  v[9],  v[10], v[11]);
    dst[3] = make_float4(v[12], v[13], v[14], v[15]);
}

// ---------------------------------------------------------------------------
// Unpack: NHWC state buffer 0 -> d_out = [out (B,1,H,W) ; x_final (B,C,H,W)]
// ---------------------------------------------------------------------------
__global__ void nca_unpack_kernel(float* __restrict__ out)
{
    int p = blockIdx.x * 256 + threadIdx.x;
    if (p >= NPIX) return;
    int b  = p >> 16;
    int hw = p & 65535;
    const float4* src = reinterpret_cast<const float4*>(g_state[0] + ((size_t)p << 4));
    float4 a0 = src[0], a1 = src[1], a2 = src[2], a3 = src[3];
    float v[CCH] = {a0.x,a0.y,a0.z,a0.w, a1.x,a1.y,a1.z,a1.w,
                    a2.x,a2.y,a2.z,a2.w, a3.x,a3.y,a3.z,a3.w};
    // out = x_final[:, 3:4, :, :]
    out[((size_t)b << 16) + hw] = v[3];
    float* xf = out + NPIX;
#pragma unroll
    for (int c = 0; c < CCH; ++c)
        xf[((size_t)(b * CCH + c) << 16) + hw] = v[c];  // coalesced per c
}

// ---------------------------------------------------------------------------
// One NCA step. src selects the read buffer; writes src^1.
// SMEM layout (floats):
//   [0      , 6144) w_fc0 (48 x 128)
//   [6144   , 8192) w_fc1 (128 x 16)
//   [8192   , 8320) b_fc0 (128)
//   [8320   , 8464) w_p0  (3*3*16)
//   [8464   , 8608) w_p1  (3*3*16)
//   [8608   , 8608 + 128*49) per-thread perception scratch (pad 49 -> no conflicts)
// ---------------------------------------------------------------------------
#define SMEM_FLOATS (6144 + 2048 + 128 + 144 + 144 + 128 * 49)
#define SMEM_BYTES  (SMEM_FLOATS * 4)

__global__ void __launch_bounds__(128)
nca_step_kernel(int src,
                const float* __restrict__ w_p0, const float* __restrict__ w_p1,
                const float* __restrict__ w_fc0, const float* __restrict__ b_fc0,
                const float* __restrict__ w_fc1,
                uint32_t key0, uint32_t key1)
{
    extern __shared__ float sm[];
    float* s_w0   = sm;            // 6144
    float* s_w1   = sm + 6144;     // 2048
    float* s_b    = sm + 8192;     // 128
    float* s_p0   = sm + 8320;     // 144
    float* s_p1   = sm + 8464;     // 144
    float* s_perc = sm + 8608;     // 128*49

    const float* cur = g_state[src];
    float*       nxt = g_state[src ^ 1];

    const int tid = threadIdx.x;
    for (int i = tid; i < 6144; i += 128) s_w0[i] = w_fc0[i];
    for (int i = tid; i < 2048; i += 128) s_w1[i] = w_fc1[i];
    s_b[tid] = b_fc0[tid];
    for (int i = tid; i < 144; i += 128) { s_p0[i] = w_p0[i]; s_p1[i] = w_p1[i]; }
    __syncthreads();

    const int p  = blockIdx.x * 128 + tid;
    const int bb = p >> 16;
    const int h  = (p >> 8) & 255;
    const int w  = p & 255;
    const float* base = cur + ((size_t)bb << 20);   // bb * 256*256*16

    // ---- perception: center + two depthwise 3x3 convs (reflect padding) ----
    float c0[CCH], c1[CCH], cen[CCH];
#pragma unroll
    for (int c = 0; c < CCH; ++c) { c0[c] = 0.f; c1[c] = 0.f; }

#pragma unroll
    for (int dh = -1; dh <= 1; ++dh) {
        int hh = h + dh; hh = (hh < 0) ? 1 : ((hh > 255) ? 254 : hh);
#pragma unroll
        for (int dw = -1; dw <= 1; ++dw) {
            int ww = w + dw; ww = (ww < 0) ? 1 : ((ww > 255) ? 254 : ww);
            const float4* px = reinterpret_cast<const float4*>(
                base + (((size_t)((hh << 8) | ww)) << 4));
            float4 v0 = px[0], v1 = px[1], v2 = px[2], v3 = px[3];
            float vv[CCH] = {v0.x,v0.y,v0.z,v0.w, v1.x,v1.y,v1.z,v1.w,
                             v2.x,v2.y,v2.z,v2.w, v3.x,v3.y,v3.z,v3.w};
            const int tap = (dh + 1) * 3 + (dw + 1);
            const float* wp0 = s_p0 + tap * 16;
            const float* wp1 = s_p1 + tap * 16;
#pragma unroll
            for (int c = 0; c < CCH; ++c) {
                c0[c] = fmaf(vv[c], wp0[c], c0[c]);
                c1[c] = fmaf(vv[c], wp1[c], c1[c]);
            }
            if (dh == 0 && dw == 0) {
#pragma unroll
                for (int c = 0; c < CCH; ++c) cen[c] = vv[c];
            }
        }
    }

    // stash perception vector in padded smem (per-thread private, no sync needed)
    float* mp = s_perc + tid * 49;
#pragma unroll
    for (int c = 0; c < CCH; ++c) {
        mp[c]      = cen[c];
        mp[16 + c] = c0[c];
        mp[32 + c] = c1[c];
    }

    // ---- MLP: h = relu(perc @ W0 + b); dx = h @ W1 (fused, 4 chunks of 32) ----
    float dx[CCH];
#pragma unroll
    for (int o = 0; o < CCH; ++o) dx[o] = 0.f;

#pragma unroll 1
    for (int chunk = 0; chunk < 4; ++chunk) {
        float hreg[32];
        {
            const float4* bbv = reinterpret_cast<const float4*>(s_b + chunk * 32);
#pragma unroll
            for (int q = 0; q < 8; ++q) {
                float4 t = bbv[q];
                hreg[4*q+0] = t.x; hreg[4*q+1] = t.y;
                hreg[4*q+2] = t.z; hreg[4*q+3] = t.w;
            }
        }
#pragma unroll 1
        for (int c = 0; c < 48; ++c) {
            float pc = mp[c];
            const float4* wr = reinterpret_cast<const float4*>(
                s_w0 + c * HID + chunk * 32);
#pragma unroll
            for (int q = 0; q < 8; ++q) {
                float4 wv = wr[q];
                hreg[4*q+0] = fmaf(pc, wv.x, hreg[4*q+0]);
                hreg[4*q+1] = fmaf(pc, wv.y, hreg[4*q+1]);
                hreg[4*q+2] = fmaf(pc, wv.z, hreg[4*q+2]);
                hreg[4*q+3] = fmaf(pc, wv.w, hreg[4*q+3]);
            }
        }
#pragma unroll
        for (int j = 0; j < 32; ++j) {
            float hj = fmaxf(hreg[j], 0.f);
            const float4* w1r = reinterpret_cast<const float4*>(
                s_w1 + ((chunk * 32 + j) << 4));
            float4 a = w1r[0], b2 = w1r[1], c2 = w1r[2], d2 = w1r[3];
            dx[0]  = fmaf(hj, a.x,  dx[0]);  dx[1]  = fmaf(hj, a.y,  dx[1]);
            dx[2]  = fmaf(hj, a.z,  dx[2]);  dx[3]  = fmaf(hj, a.w,  dx[3]);
            dx[4]  = fmaf(hj, b2.x, dx[4]);  dx[5]  = fmaf(hj, b2.y, dx[5]);
            dx[6]  = fmaf(hj, b2.z, dx[6]);  dx[7]  = fmaf(hj, b2.w, dx[7]);
            dx[8]  = fmaf(hj, c2.x, dx[8]);  dx[9]  = fmaf(hj, c2.y, dx[9]);
            dx[10] = fmaf(hj, c2.z, dx[10]); dx[11] = fmaf(hj, c2.w, dx[11]);
            dx[12] = fmaf(hj, d2.x, dx[12]); dx[13] = fmaf(hj, d2.y, dx[13]);
            dx[14] = fmaf(hj, d2.z, dx[14]); dx[15] = fmaf(hj, d2.w, dx[15]);
        }
    }

    // ---- stochastic fire mask: JAX partitionable threefry counter = flat idx ----
    uint32_t r0, r1;
    threefry2x32(key0, key1, 0u, (uint32_t)p, r0, r1);
    uint32_t bits = r0 ^ r1;
    float u = __uint_as_float((bits >> 9) | 0x3f800000u) - 1.0f;
    float m = (u <= 0.5f) ? 1.0f : 0.0f;

    // ---- residual update; channels 0..2 pinned to original image ----
    float outv[CCH];
#pragma unroll
    for (int c = 0; c < CCH; ++c) {
        float oldv = mp[c];
        float nv   = fmaf(dx[c], m, oldv);
        outv[c]    = (c < 3) ? oldv : nv;
    }
    float4* dst = reinterpret_cast<float4*>(nxt + ((size_t)p << 4));
    dst[0] = make_float4(outv[0],  outv[1],  outv[2],  outv[3]);
    dst[1] = make_float4(outv[4],  outv[5],  outv[6],  outv[7]);
    dst[2] = make_float4(outv[8],  outv[9],  outv[10], outv[11]);
    dst[3] = make_float4(outv[12], outv[13], outv[14], outv[15]);
}

// ---------------------------------------------------------------------------
// Launch
// ---------------------------------------------------------------------------
extern "C" void kernel_launch(void* const* d_in, const int* in_sizes, int n_in,
                              void* d_out, int out_size)
{
    const float* x      = (const float*)d_in[0];
    const float* w_p0   = (const float*)d_in[1];
    const float* w_p1   = (const float*)d_in[2];
    const float* w_fc0  = (const float*)d_in[3];
    const float* b_fc0  = (const float*)d_in[4];
    const float* w_fc1  = (const float*)d_in[5];
    float* out = (float*)d_out;

    // step keys: jax.random.split(jax.random.key(42), 32), partitionable
    // (foldlike): key_j = threefry(key=(0,42), x0=0, x1=j) -> (o0, o1)
    uint32_t k0s[STEPS], k1s[STEPS];
    for (int j = 0; j < STEPS; ++j) {
        uint32_t a, b;
        threefry2x32(0u, 42u, 0u, (uint32_t)j, a, b);
        k0s[j] = a; k1s[j] = b;
    }

    cudaFuncSetAttribute(nca_step_kernel,
                         cudaFuncAttributeMaxDynamicSharedMemorySize, SMEM_BYTES);

    nca_pack_kernel<<<NPIX / 256, 256>>>(x);
    for (int s = 0; s < STEPS; ++s) {
        nca_step_kernel<<<NPIX / 128, 128, SMEM_BYTES>>>(
            s & 1, w_p0, w_p1, w_fc0, b_fc0, w_fc1, k0s[s], k1s[s]);
    }
    nca_unpack_kernel<<<NPIX / 256, 256>>>(out);
}

// round 3
// speedup vs baseline: 1.8072x; 1.8072x over previous
#include <cuda_runtime.h>
#include <cstdint>

// ---------------------------------------------------------------------------
// Problem constants
// ---------------------------------------------------------------------------
#define BATCH 8
#define IMG   256
#define CCH   16
#define HID   128
#define NPIX  (BATCH * IMG * IMG)          // 524288 pixels
#define STATE_ELEMS (NPIX * CCH)
#define STEPS 32

typedef unsigned long long u64;

// ping-pong state buffers (NHWC), static device memory (no allocation)
__device__ float g_state[2][STATE_ELEMS];
// active-pixel compaction (one list reused per step; 32 counters)
__device__ int g_list[NPIX];
__device__ int g_cnt[STEPS];

// ---------------------------------------------------------------------------
// packed f32x2 helpers (bit-exact: two independent rn fp32 FMAs)
// ---------------------------------------------------------------------------
static __device__ __forceinline__ u64 pack2dup(float x) {
    u64 r; asm("mov.b64 %0, {%1, %1};" : "=l"(r) : "f"(x)); return r;
}
static __device__ __forceinline__ void ffma2(u64& acc, u64 a, u64 b) {
    asm("fma.rn.f32x2 %0, %1, %2, %0;" : "+l"(acc) : "l"(a), "l"(b));
}
static __device__ __forceinline__ float2 unpack2(u64 v) {
    float2 f; asm("mov.b64 {%0, %1}, %2;" : "=f"(f.x), "=f"(f.y) : "l"(v)); return f;
}

// ---------------------------------------------------------------------------
// Threefry-2x32 (20 rounds) — exact JAX implementation
// ---------------------------------------------------------------------------
static __host__ __device__ __forceinline__ uint32_t tf_rotl(uint32_t v, int r) {
    return (v << r) | (v >> (32 - r));
}
static __host__ __device__ __forceinline__ void threefry2x32(
    uint32_t k0, uint32_t k1, uint32_t x0, uint32_t x1,
    uint32_t& o0, uint32_t& o1)
{
    uint32_t ks2 = k0 ^ k1 ^ 0x1BD11BDAu;
    x0 += k0; x1 += k1;
    x0 += x1; x1 = tf_rotl(x1, 13); x1 ^= x0;
    x0 += x1; x1 = tf_rotl(x1, 15); x1 ^= x0;
    x0 += x1; x1 = tf_rotl(x1, 26); x1 ^= x0;
    x0 += x1; x1 = tf_rotl(x1,  6); x1 ^= x0;
    x0 += k1; x1 += ks2 + 1u;
    x0 += x1; x1 = tf_rotl(x1, 17); x1 ^= x0;
    x0 += x1; x1 = tf_rotl(x1, 29); x1 ^= x0;
    x0 += x1; x1 = tf_rotl(x1, 16); x1 ^= x0;
    x0 += x1; x1 = tf_rotl(x1, 24); x1 ^= x0;
    x0 += ks2; x1 += k0 + 2u;
    x0 += x1; x1 = tf_rotl(x1, 13); x1 ^= x0;
    x0 += x1; x1 = tf_rotl(x1, 15); x1 ^= x0;
    x0 += x1; x1 = tf_rotl(x1, 26); x1 ^= x0;
    x0 += x1; x1 = tf_rotl(x1,  6); x1 ^= x0;
    x0 += k0; x1 += k1 + 3u;
    x0 += x1; x1 = tf_rotl(x1, 17); x1 ^= x0;
    x0 += x1; x1 = tf_rotl(x1, 29); x1 ^= x0;
    x0 += x1; x1 = tf_rotl(x1, 16); x1 ^= x0;
    x0 += x1; x1 = tf_rotl(x1, 24); x1 ^= x0;
    x0 += k1; x1 += ks2 + 4u;
    x0 += x1; x1 = tf_rotl(x1, 13); x1 ^= x0;
    x0 += x1; x1 = tf_rotl(x1, 15); x1 ^= x0;
    x0 += x1; x1 = tf_rotl(x1, 26); x1 ^= x0;
    x0 += x1; x1 = tf_rotl(x1,  6); x1 ^= x0;
    x0 += ks2; x1 += k0 + 5u;
    o0 = x0; o1 = x1;
}

// ---------------------------------------------------------------------------
// Pack: NCHW input -> NHWC state buffer 0; also zero the step counters
// ---------------------------------------------------------------------------
__global__ void nca_pack_kernel(const float* __restrict__ x)
{
    int p = blockIdx.x * 256 + threadIdx.x;
    if (blockIdx.x == 0 && threadIdx.x < STEPS) g_cnt[threadIdx.x] = 0;
    if (p >= NPIX) return;
    int b  = p >> 16;
    int hw = p & 65535;
    float v[CCH];
#pragma unroll
    for (int c = 0; c < CCH; ++c)
        v[c] = x[((size_t)(b * CCH + c) << 16) + hw];
    float4* dst = reinterpret_cast<float4*>(g_state[0] + ((size_t)p << 4));
    dst[0] = make_float4(v[0],  v[1],  v[2],  v[3]);
    dst[1] = make_float4(v[4],  v[5],  v[6],  v[7]);
    dst[2] = make_float4(v[8],  v[9],  v[10], v[11]);
    dst[3] = make_float4(v[12], v[13], v[14], v[15]);
}

// ---------------------------------------------------------------------------
// Unpack: state buffer 0 -> d_out = [out (B,1,H,W) ; x_final (B,C,H,W)]
// ---------------------------------------------------------------------------
__global__ void nca_unpack_kernel(float* __restrict__ out)
{
    int p = blockIdx.x * 256 + threadIdx.x;
    if (p >= NPIX) return;
    int b  = p >> 16;
    int hw = p & 65535;
    const float4* src = reinterpret_cast<const float4*>(g_state[0] + ((size_t)p << 4));
    float4 a0 = src[0], a1 = src[1], a2 = src[2], a3 = src[3];
    float v[CCH] = {a0.x,a0.y,a0.z,a0.w, a1.x,a1.y,a1.z,a1.w,
                    a2.x,a2.y,a2.z,a2.w, a3.x,a3.y,a3.z,a3.w};
    out[((size_t)b << 16) + hw] = v[3];
    float* xf = out + NPIX;
#pragma unroll
    for (int c = 0; c < CCH; ++c)
        xf[((size_t)(b * CCH + c) << 16) + hw] = v[c];
}

// ---------------------------------------------------------------------------
// Kernel A: per-step fire mask + compaction. Inactive pixels are copied
// through (xn == xc when mask==0, since channels 0..2 are invariant).
// Active pixel indices go into g_list (count in g_cnt[step]).
// ---------------------------------------------------------------------------
__global__ void nca_mask_kernel(int src, int step, uint32_t key0, uint32_t key1)
{
    int p = blockIdx.x * 256 + threadIdx.x;
    const int lane = threadIdx.x & 31;

    uint32_t r0, r1;
    threefry2x32(key0, key1, 0u, (uint32_t)p, r0, r1);
    uint32_t bits = r0 ^ r1;
    float u = __uint_as_float((bits >> 9) | 0x3f800000u) - 1.0f;
    bool active = (u <= 0.5f);

    unsigned ball = __ballot_sync(0xffffffffu, active);
    int nact = __popc(ball);
    int rank = __popc(ball & ((1u << lane) - 1u));
    int base = 0;
    if (lane == 0 && nact > 0) base = atomicAdd(&g_cnt[step], nact);
    base = __shfl_sync(0xffffffffu, base, 0);

    if (active) {
        g_list[base + rank] = p;
    } else {
        // copy-through
        const float4* s = reinterpret_cast<const float4*>(g_state[src] + ((size_t)p << 4));
        float4* d = reinterpret_cast<float4*>(g_state[src ^ 1] + ((size_t)p << 4));
        d[0] = s[0]; d[1] = s[1]; d[2] = s[2]; d[3] = s[3];
    }
}

// ---------------------------------------------------------------------------
// Kernel B: MLP update for active pixels only (gathered via g_list).
// SMEM: weights only (34.4 KB). Perception kept in registers, math packed
// as fp32x2 (bit-exact).
// ---------------------------------------------------------------------------
#define SMEM_FLOATS (6144 + 2048 + 128 + 144 + 144)
#define SMEM_BYTES  (SMEM_FLOATS * 4)
#define UPD_BLOCKS  2048

__global__ void __launch_bounds__(128)
nca_update_kernel(int src, int step,
                  const float* __restrict__ w_p0, const float* __restrict__ w_p1,
                  const float* __restrict__ w_fc0, const float* __restrict__ b_fc0,
                  const float* __restrict__ w_fc1)
{
    extern __shared__ float sm[];
    float* s_w0 = sm;            // 6144
    float* s_w1 = sm + 6144;     // 2048
    float* s_b  = sm + 8192;     // 128
    float* s_p0 = sm + 8320;     // 144
    float* s_p1 = sm + 8464;     // 144

    const float* cur = g_state[src];
    float*       nxt = g_state[src ^ 1];

    const int tid = threadIdx.x;
    for (int i = tid; i < 6144; i += 128) s_w0[i] = w_fc0[i];
    for (int i = tid; i < 2048; i += 128) s_w1[i] = w_fc1[i];
    s_b[tid] = b_fc0[tid];
    for (int i = tid; i < 144; i += 128) { s_p0[i] = w_p0[i]; s_p1[i] = w_p1[i]; }
    __syncthreads();

    const int count = g_cnt[step];

    for (int tile = blockIdx.x * 128; tile < count; tile += UPD_BLOCKS * 128) {
        int i = tile + tid;
        if (i >= count) continue;
        int p = g_list[i];

        const int bb = p >> 16;
        const int h  = (p >> 8) & 255;
        const int w  = p & 255;
        const float* base = cur + ((size_t)bb << 20);

        // ---- perception (packed): center + 2 depthwise 3x3 reflect convs ----
        float perc[48];
        u64 c0a[8], c1a[8];
#pragma unroll
        for (int k = 0; k < 8; ++k) { c0a[k] = 0ull; c1a[k] = 0ull; }

#pragma unroll
        for (int dh = -1; dh <= 1; ++dh) {
            int hh = h + dh; hh = (hh < 0) ? 1 : ((hh > 255) ? 254 : hh);
#pragma unroll
            for (int dw = -1; dw <= 1; ++dw) {
                int ww = w + dw; ww = (ww < 0) ? 1 : ((ww > 255) ? 254 : ww);
                const ulonglong2* px = reinterpret_cast<const ulonglong2*>(
                    base + (((size_t)((hh << 8) | ww)) << 4));
                ulonglong2 q0 = px[0], q1 = px[1], q2 = px[2], q3 = px[3];
                u64 vv[8] = {q0.x, q0.y, q1.x, q1.y, q2.x, q2.y, q3.x, q3.y};
                const int tap = (dh + 1) * 3 + (dw + 1);
                const ulonglong2* wp0 = reinterpret_cast<const ulonglong2*>(s_p0 + tap * 16);
                const ulonglong2* wp1 = reinterpret_cast<const ulonglong2*>(s_p1 + tap * 16);
#pragma unroll
                for (int q = 0; q < 4; ++q) {
                    ulonglong2 a = wp0[q], b = wp1[q];
                    ffma2(c0a[2*q],   vv[2*q],   a.x);
                    ffma2(c0a[2*q+1], vv[2*q+1], a.y);
                    ffma2(c1a[2*q],   vv[2*q],   b.x);
                    ffma2(c1a[2*q+1], vv[2*q+1], b.y);
                }
                if (dh == 0 && dw == 0) {
#pragma unroll
                    for (int q = 0; q < 8; ++q) {
                        float2 f = unpack2(vv[q]);
                        perc[2*q] = f.x; perc[2*q+1] = f.y;
                    }
                }
            }
        }
#pragma unroll
        for (int k = 0; k < 8; ++k) {
            float2 a = unpack2(c0a[k]);
            float2 b = unpack2(c1a[k]);
            perc[16 + 2*k] = a.x; perc[16 + 2*k + 1] = a.y;
            perc[32 + 2*k] = b.x; perc[32 + 2*k + 1] = b.y;
        }

        // ---- fused MLP: h = relu(perc @ W0 + b); dx = h @ W1 (packed) ----
        u64 dx2[8];
#pragma unroll
        for (int k = 0; k < 8; ++k) dx2[k] = 0ull;

#pragma unroll 1
        for (int chunk = 0; chunk < 4; ++chunk) {
            u64 h2[16];
            {
                const ulonglong2* bv = reinterpret_cast<const ulonglong2*>(s_b + chunk * 32);
#pragma unroll
                for (int q = 0; q < 8; ++q) {
                    ulonglong2 t = bv[q];
                    h2[2*q] = t.x; h2[2*q+1] = t.y;
                }
            }
#pragma unroll
            for (int c = 0; c < 48; ++c) {
                u64 pc2 = pack2dup(perc[c]);
                const ulonglong2* wr = reinterpret_cast<const ulonglong2*>(
                    s_w0 + c * HID + chunk * 32);
#pragma unroll
                for (int q = 0; q < 8; ++q) {
                    ulonglong2 t = wr[q];
                    ffma2(h2[2*q],   pc2, t.x);
                    ffma2(h2[2*q+1], pc2, t.y);
                }
            }
            // relu + second layer
#pragma unroll
            for (int jj = 0; jj < 16; ++jj) {
                float2 hp = unpack2(h2[jj]);
                float ha = fmaxf(hp.x, 0.f);
                float hb = fmaxf(hp.y, 0.f);
                u64 ha2 = pack2dup(ha);
                u64 hb2 = pack2dup(hb);
                int j0 = chunk * 32 + 2 * jj;
                const ulonglong2* w1a = reinterpret_cast<const ulonglong2*>(s_w1 + (j0 << 4));
                const ulonglong2* w1b = reinterpret_cast<const ulonglong2*>(s_w1 + ((j0 + 1) << 4));
#pragma unroll
                for (int q = 0; q < 4; ++q) {
                    ulonglong2 ta = w1a[q];
                    ffma2(dx2[2*q],   ha2, ta.x);
                    ffma2(dx2[2*q+1], ha2, ta.y);
                }
#pragma unroll
                for (int q = 0; q < 4; ++q) {
                    ulonglong2 tb = w1b[q];
                    ffma2(dx2[2*q],   hb2, tb.x);
                    ffma2(dx2[2*q+1], hb2, tb.y);
                }
            }
        }

        // ---- residual update (mask==1 here); channels 0..2 pinned ----
        float outv[CCH];
#pragma unroll
        for (int k = 0; k < 8; ++k) {
            float2 d = unpack2(dx2[k]);
            outv[2*k]   = perc[2*k]   + d.x;
            outv[2*k+1] = perc[2*k+1] + d.y;
        }
        outv[0] = perc[0]; outv[1] = perc[1]; outv[2] = perc[2];

        float4* dst = reinterpret_cast<float4*>(nxt + ((size_t)p << 4));
        dst[0] = make_float4(outv[0],  outv[1],  outv[2],  outv[3]);
        dst[1] = make_float4(outv[4],  outv[5],  outv[6],  outv[7]);
        dst[2] = make_float4(outv[8],  outv[9],  outv[10], outv[11]);
        dst[3] = make_float4(outv[12], outv[13], outv[14], outv[15]);
    }
}

// ---------------------------------------------------------------------------
// Launch
// ---------------------------------------------------------------------------
extern "C" void kernel_launch(void* const* d_in, const int* in_sizes, int n_in,
                              void* d_out, int out_size)
{
    const float* x      = (const float*)d_in[0];
    const float* w_p0   = (const float*)d_in[1];
    const float* w_p1   = (const float*)d_in[2];
    const float* w_fc0  = (const float*)d_in[3];
    const float* b_fc0  = (const float*)d_in[4];
    const float* w_fc1  = (const float*)d_in[5];
    float* out = (float*)d_out;

    // step keys: jax.random.split(jax.random.key(42), 32) (partitionable)
    uint32_t k0s[STEPS], k1s[STEPS];
    for (int j = 0; j < STEPS; ++j) {
        uint32_t a, b;
        threefry2x32(0u, 42u, 0u, (uint32_t)j, a, b);
        k0s[j] = a; k1s[j] = b;
    }

    cudaFuncSetAttribute(nca_update_kernel,
                         cudaFuncAttributeMaxDynamicSharedMemorySize, SMEM_BYTES);

    nca_pack_kernel<<<NPIX / 256, 256>>>(x);
    for (int s = 0; s < STEPS; ++s) {
        nca_mask_kernel<<<NPIX / 256, 256>>>(s & 1, s, k0s[s], k1s[s]);
        nca_update_kernel<<<UPD_BLOCKS, 128, SMEM_BYTES>>>(
            s & 1, s, w_p0, w_p1, w_fc0, b_fc0, w_fc1);
    }
    nca_unpack_kernel<<<NPIX / 256, 256>>>(out);
}

// round 4
// speedup vs baseline: 2.4284x; 1.3437x over previous
#include <cuda_runtime.h>
#include <cstdint>

// ---------------------------------------------------------------------------
// Problem constants
// ---------------------------------------------------------------------------
#define BATCH 8
#define IMG   256
#define CCH   16
#define HID   128
#define NPIX  (BATCH * IMG * IMG)          // 524288 pixels
#define STATE_ELEMS (NPIX * CCH)
#define STEPS 32
#define LIST_CAP (NPIX / 2 + 8192)         // binomial(NPIX,0.5) +/- ~2k

typedef unsigned long long u64;

// ping-pong state buffers (NHWC), static device memory (no allocation)
__device__ float g_state[2][STATE_ELEMS];
// per-step compacted active / inactive pixel lists
__device__ int g_list[STEPS][LIST_CAP];
__device__ int g_ilist[STEPS][LIST_CAP];
__device__ int g_cnt[STEPS];
__device__ int g_icnt[STEPS];

struct KeyArr { uint32_t k0[STEPS]; uint32_t k1[STEPS]; };

// ---------------------------------------------------------------------------
// packed f32x2 helpers (bit-exact: two independent rn fp32 FMAs)
// ---------------------------------------------------------------------------
static __device__ __forceinline__ u64 pack2dup(float x) {
    u64 r; asm("mov.b64 %0, {%1, %1};" : "=l"(r) : "f"(x)); return r;
}
static __device__ __forceinline__ void ffma2(u64& acc, u64 a, u64 b) {
    asm("fma.rn.f32x2 %0, %1, %2, %0;" : "+l"(acc) : "l"(a), "l"(b));
}
static __device__ __forceinline__ float2 unpack2(u64 v) {
    float2 f; asm("mov.b64 {%0, %1}, %2;" : "=f"(f.x), "=f"(f.y) : "l"(v)); return f;
}

// ---------------------------------------------------------------------------
// Threefry-2x32 (20 rounds) — exact JAX implementation
// ---------------------------------------------------------------------------
static __host__ __device__ __forceinline__ uint32_t tf_rotl(uint32_t v, int r) {
    return (v << r) | (v >> (32 - r));
}
static __host__ __device__ __forceinline__ void threefry2x32(
    uint32_t k0, uint32_t k1, uint32_t x0, uint32_t x1,
    uint32_t& o0, uint32_t& o1)
{
    uint32_t ks2 = k0 ^ k1 ^ 0x1BD11BDAu;
    x0 += k0; x1 += k1;
    x0 += x1; x1 = tf_rotl(x1, 13); x1 ^= x0;
    x0 += x1; x1 = tf_rotl(x1, 15); x1 ^= x0;
    x0 += x1; x1 = tf_rotl(x1, 26); x1 ^= x0;
    x0 += x1; x1 = tf_rotl(x1,  6); x1 ^= x0;
    x0 += k1; x1 += ks2 + 1u;
    x0 += x1; x1 = tf_rotl(x1, 17); x1 ^= x0;
    x0 += x1; x1 = tf_rotl(x1, 29); x1 ^= x0;
    x0 += x1; x1 = tf_rotl(x1, 16); x1 ^= x0;
    x0 += x1; x1 = tf_rotl(x1, 24); x1 ^= x0;
    x0 += ks2; x1 += k0 + 2u;
    x0 += x1; x1 = tf_rotl(x1, 13); x1 ^= x0;
    x0 += x1; x1 = tf_rotl(x1, 15); x1 ^= x0;
    x0 += x1; x1 = tf_rotl(x1, 26); x1 ^= x0;
    x0 += x1; x1 = tf_rotl(x1,  6); x1 ^= x0;
    x0 += k0; x1 += k1 + 3u;
    x0 += x1; x1 = tf_rotl(x1, 17); x1 ^= x0;
    x0 += x1; x1 = tf_rotl(x1, 29); x1 ^= x0;
    x0 += x1; x1 = tf_rotl(x1, 16); x1 ^= x0;
    x0 += x1; x1 = tf_rotl(x1, 24); x1 ^= x0;
    x0 += k1; x1 += ks2 + 4u;
    x0 += x1; x1 = tf_rotl(x1, 13); x1 ^= x0;
    x0 += x1; x1 = tf_rotl(x1, 15); x1 ^= x0;
    x0 += x1; x1 = tf_rotl(x1, 26); x1 ^= x0;
    x0 += x1; x1 = tf_rotl(x1,  6); x1 ^= x0;
    x0 += ks2; x1 += k0 + 5u;
    o0 = x0; o1 = x1;
}

// ---------------------------------------------------------------------------
// Pack: NCHW input -> NHWC state buffer 0; zero all list counters
// ---------------------------------------------------------------------------
__global__ void nca_pack_kernel(const float* __restrict__ x)
{
    int p = blockIdx.x * 256 + threadIdx.x;
    if (blockIdx.x == 0 && threadIdx.x < STEPS) {
        g_cnt[threadIdx.x] = 0;
        g_icnt[threadIdx.x] = 0;
    }
    if (p >= NPIX) return;
    int b  = p >> 16;
    int hw = p & 65535;
    float v[CCH];
#pragma unroll
    for (int c = 0; c < CCH; ++c)
        v[c] = x[((size_t)(b * CCH + c) << 16) + hw];
    float4* dst = reinterpret_cast<float4*>(g_state[0] + ((size_t)p << 4));
    dst[0] = make_float4(v[0],  v[1],  v[2],  v[3]);
    dst[1] = make_float4(v[4],  v[5],  v[6],  v[7]);
    dst[2] = make_float4(v[8],  v[9],  v[10], v[11]);
    dst[3] = make_float4(v[12], v[13], v[14], v[15]);
}

// ---------------------------------------------------------------------------
// All 32 fire masks in one pass: build compacted active/inactive lists.
// ---------------------------------------------------------------------------
__global__ void nca_maskall_kernel(KeyArr keys)
{
    int p = blockIdx.x * 256 + threadIdx.x;
    const int lane = threadIdx.x & 31;

#pragma unroll 1
    for (int s = 0; s < STEPS; ++s) {
        uint32_t r0, r1;
        threefry2x32(keys.k0[s], keys.k1[s], 0u, (uint32_t)p, r0, r1);
        uint32_t bits = r0 ^ r1;
        float u = __uint_as_float((bits >> 9) | 0x3f800000u) - 1.0f;
        bool active = (u <= 0.5f);

        unsigned ball = __ballot_sync(0xffffffffu, active);
        int nact = __popc(ball);
        int rank = __popc(ball & ((1u << lane) - 1u));
        int baseA = 0, baseI = 0;
        if (lane == 0) {
            if (nact > 0)  baseA = atomicAdd(&g_cnt[s], nact);
            if (nact < 32) baseI = atomicAdd(&g_icnt[s], 32 - nact);
        }
        baseA = __shfl_sync(0xffffffffu, baseA, 0);
        baseI = __shfl_sync(0xffffffffu, baseI, 0);
        if (active) g_list[s][baseA + rank] = p;
        else        g_ilist[s][baseI + (lane - rank)] = p;
    }
}

// ---------------------------------------------------------------------------
// Per-step fused kernel:
//   blocks [0, UPD_BLOCKS)          : MLP update for active pixels (2 px/thread)
//   blocks [UPD_BLOCKS, TOT_BLOCKS) : copy-through for inactive pixels
// ---------------------------------------------------------------------------
#define SMEM_FLOATS (6144 + 2048 + 128 + 144 + 144)
#define SMEM_BYTES  (SMEM_FLOATS * 4)
#define UPD_BLOCKS  1024
#define CPY_BLOCKS  256
#define TOT_BLOCKS  (UPD_BLOCKS + CPY_BLOCKS)

// perception for one pixel: perc[0:16]=center, [16:32]=conv0, [32:48]=conv1
static __device__ __forceinline__ void perception(
    const float* __restrict__ base, int h, int w,
    const float* __restrict__ s_p0, const float* __restrict__ s_p1,
    float* __restrict__ perc)
{
    u64 c0a[8], c1a[8];
#pragma unroll
    for (int k = 0; k < 8; ++k) { c0a[k] = 0ull; c1a[k] = 0ull; }

#pragma unroll
    for (int dh = -1; dh <= 1; ++dh) {
        int hh = h + dh; hh = (hh < 0) ? 1 : ((hh > 255) ? 254 : hh);
#pragma unroll
        for (int dw = -1; dw <= 1; ++dw) {
            int ww = w + dw; ww = (ww < 0) ? 1 : ((ww > 255) ? 254 : ww);
            const ulonglong2* px = reinterpret_cast<const ulonglong2*>(
                base + (((size_t)((hh << 8) | ww)) << 4));
            ulonglong2 q0 = px[0], q1 = px[1], q2 = px[2], q3 = px[3];
            u64 vv[8] = {q0.x, q0.y, q1.x, q1.y, q2.x, q2.y, q3.x, q3.y};
            const int tap = (dh + 1) * 3 + (dw + 1);
            const ulonglong2* wp0 = reinterpret_cast<const ulonglong2*>(s_p0 + tap * 16);
            const ulonglong2* wp1 = reinterpret_cast<const ulonglong2*>(s_p1 + tap * 16);
#pragma unroll
            for (int q = 0; q < 4; ++q) {
                ulonglong2 a = wp0[q], b = wp1[q];
                ffma2(c0a[2*q],   vv[2*q],   a.x);
                ffma2(c0a[2*q+1], vv[2*q+1], a.y);
                ffma2(c1a[2*q],   vv[2*q],   b.x);
                ffma2(c1a[2*q+1], vv[2*q+1], b.y);
            }
            if (dh == 0 && dw == 0) {
#pragma unroll
                for (int q = 0; q < 8; ++q) {
                    float2 f = unpack2(vv[q]);
                    perc[2*q] = f.x; perc[2*q+1] = f.y;
                }
            }
        }
    }
#pragma unroll
    for (int k = 0; k < 8; ++k) {
        float2 a = unpack2(c0a[k]);
        float2 b = unpack2(c1a[k]);
        perc[16 + 2*k] = a.x; perc[16 + 2*k + 1] = a.y;
        perc[32 + 2*k] = b.x; perc[32 + 2*k + 1] = b.y;
    }
}

__global__ void __launch_bounds__(128, 2)
nca_step_kernel(int src, int step,
                const float* __restrict__ w_p0, const float* __restrict__ w_p1,
                const float* __restrict__ w_fc0, const float* __restrict__ b_fc0,
                const float* __restrict__ w_fc1)
{
    const float* cur = g_state[src];
    float*       nxt = g_state[src ^ 1];
    const int tid = threadIdx.x;

    // ---------------- inactive copy-through blocks ----------------
    if (blockIdx.x >= UPD_BLOCKS) {
        const int icnt = g_icnt[step];
        const int* il = g_ilist[step];
        for (int i = (blockIdx.x - UPD_BLOCKS) * 128 + tid; i < icnt;
             i += CPY_BLOCKS * 128) {
            int p = il[i];
            const float4* s = reinterpret_cast<const float4*>(cur + ((size_t)p << 4));
            float4* d = reinterpret_cast<float4*>(nxt + ((size_t)p << 4));
            d[0] = s[0]; d[1] = s[1]; d[2] = s[2]; d[3] = s[3];
        }
        return;
    }

    // ---------------- active MLP blocks ----------------
    extern __shared__ float sm[];
    float* s_w0 = sm;            // 6144
    float* s_w1 = sm + 6144;     // 2048
    float* s_b  = sm + 8192;     // 128
    float* s_p0 = sm + 8320;     // 144
    float* s_p1 = sm + 8464;     // 144

    for (int i = tid; i < 6144; i += 128) s_w0[i] = w_fc0[i];
    for (int i = tid; i < 2048; i += 128) s_w1[i] = w_fc1[i];
    s_b[tid] = b_fc0[tid];
    for (int i = tid; i < 144; i += 128) { s_p0[i] = w_p0[i]; s_p1[i] = w_p1[i]; }
    __syncthreads();

    const int count = g_cnt[step];
    const int* al = g_list[step];

#pragma unroll 1
    for (int base = blockIdx.x * 256; base < count; base += UPD_BLOCKS * 256) {
        int iA = base + tid;
        if (iA >= count) continue;
        int iB = base + 128 + tid;
        int pA = al[iA];
        int pB = (iB < count) ? al[iB] : pA;   // duplicate is benign

        const float* baseA = cur + ((size_t)(pA >> 16) << 20);
        const float* baseB = cur + ((size_t)(pB >> 16) << 20);

        float percA[48], percB[48];
        perception(baseA, (pA >> 8) & 255, pA & 255, s_p0, s_p1, percA);
        perception(baseB, (pB >> 8) & 255, pB & 255, s_p0, s_p1, percB);

        // ---- fused MLP over 4 chunks of 32 hidden units, 2 pixels ----
        u64 dxA[8], dxB[8];
#pragma unroll
        for (int k = 0; k < 8; ++k) { dxA[k] = 0ull; dxB[k] = 0ull; }

#pragma unroll 1
        for (int chunk = 0; chunk < 4; ++chunk) {
            u64 hA[16], hB[16];
            {
                const ulonglong2* bv = reinterpret_cast<const ulonglong2*>(s_b + chunk * 32);
#pragma unroll
                for (int q = 0; q < 8; ++q) {
                    ulonglong2 t = bv[q];
                    hA[2*q] = t.x; hA[2*q+1] = t.y;
                    hB[2*q] = t.x; hB[2*q+1] = t.y;
                }
            }
#pragma unroll
            for (int c = 0; c < 48; ++c) {
                u64 pa2 = pack2dup(percA[c]);
                u64 pb2 = pack2dup(percB[c]);
                const ulonglong2* wr = reinterpret_cast<const ulonglong2*>(
                    s_w0 + c * HID + chunk * 32);
#pragma unroll
                for (int q = 0; q < 8; ++q) {
                    ulonglong2 t = wr[q];
                    ffma2(hA[2*q],   pa2, t.x);
                    ffma2(hA[2*q+1], pa2, t.y);
                    ffma2(hB[2*q],   pb2, t.x);
                    ffma2(hB[2*q+1], pb2, t.y);
                }
            }
            // relu + second layer (weight loads shared between pixels)
#pragma unroll
            for (int jj = 0; jj < 16; ++jj) {
                float2 ha = unpack2(hA[jj]);
                float2 hb = unpack2(hB[jj]);
                u64 haA2 = pack2dup(fmaxf(ha.x, 0.f));
                u64 hbA2 = pack2dup(fmaxf(ha.y, 0.f));
                u64 haB2 = pack2dup(fmaxf(hb.x, 0.f));
                u64 hbB2 = pack2dup(fmaxf(hb.y, 0.f));
                int j0 = chunk * 32 + 2 * jj;
                const ulonglong2* w1a = reinterpret_cast<const ulonglong2*>(s_w1 + (j0 << 4));
                const ulonglong2* w1b = reinterpret_cast<const ulonglong2*>(s_w1 + ((j0 + 1) << 4));
#pragma unroll
                for (int q = 0; q < 4; ++q) {
                    ulonglong2 ta = w1a[q];
                    ffma2(dxA[2*q],   haA2, ta.x);
                    ffma2(dxA[2*q+1], haA2, ta.y);
                    ffma2(dxB[2*q],   haB2, ta.x);
                    ffma2(dxB[2*q+1], haB2, ta.y);
                }
#pragma unroll
                for (int q = 0; q < 4; ++q) {
                    ulonglong2 tb = w1b[q];
                    ffma2(dxA[2*q],   hbA2, tb.x);
                    ffma2(dxA[2*q+1], hbA2, tb.y);
                    ffma2(dxB[2*q],   hbB2, tb.x);
                    ffma2(dxB[2*q+1], hbB2, tb.y);
                }
            }
        }

        // ---- residual update; channels 0..2 pinned ----
        float outA[CCH], outB[CCH];
#pragma unroll
        for (int k = 0; k < 8; ++k) {
            float2 da = unpack2(dxA[k]);
            float2 db = unpack2(dxB[k]);
            outA[2*k]   = percA[2*k]   + da.x;
            outA[2*k+1] = percA[2*k+1] + da.y;
            outB[2*k]   = percB[2*k]   + db.x;
            outB[2*k+1] = percB[2*k+1] + db.y;
        }
        outA[0] = percA[0]; outA[1] = percA[1]; outA[2] = percA[2];
        outB[0] = percB[0]; outB[1] = percB[1]; outB[2] = percB[2];

        float4* dA = reinterpret_cast<float4*>(nxt + ((size_t)pA << 4));
        dA[0] = make_float4(outA[0],  outA[1],  outA[2],  outA[3]);
        dA[1] = make_float4(outA[4],  outA[5],  outA[6],  outA[7]);
        dA[2] = make_float4(outA[8],  outA[9],  outA[10], outA[11]);
        dA[3] = make_float4(outA[12], outA[13], outA[14], outA[15]);
        float4* dB = reinterpret_cast<float4*>(nxt + ((size_t)pB << 4));
        dB[0] = make_float4(outB[0],  outB[1],  outB[2],  outB[3]);
        dB[1] = make_float4(outB[4],  outB[5],  outB[6],  outB[7]);
        dB[2] = make_float4(outB[8],  outB[9],  outB[10], outB[11]);
        dB[3] = make_float4(outB[12], outB[13], outB[14], outB[15]);
    }
}

// ---------------------------------------------------------------------------
// Unpack: state buffer 0 -> d_out = [out (B,1,H,W) ; x_final (B,C,H,W)]
// ---------------------------------------------------------------------------
__global__ void nca_unpack_kernel(float* __restrict__ out)
{
    int p = blockIdx.x * 256 + threadIdx.x;
    if (p >= NPIX) return;
    int b  = p >> 16;
    int hw = p & 65535;
    const float4* src = reinterpret_cast<const float4*>(g_state[0] + ((size_t)p << 4));
    float4 a0 = src[0], a1 = src[1], a2 = src[2], a3 = src[3];
    float v[CCH] = {a0.x,a0.y,a0.z,a0.w, a1.x,a1.y,a1.z,a1.w,
                    a2.x,a2.y,a2.z,a2.w, a3.x,a3.y,a3.z,a3.w};
    out[((size_t)b << 16) + hw] = v[3];
    float* xf = out + NPIX;
#pragma unroll
    for (int c = 0; c < CCH; ++c)
        xf[((size_t)(b * CCH + c) << 16) + hw] = v[c];
}

// ---------------------------------------------------------------------------
// Launch
// ---------------------------------------------------------------------------
extern "C" void kernel_launch(void* const* d_in, const int* in_sizes, int n_in,
                              void* d_out, int out_size)
{
    const float* x      = (const float*)d_in[0];
    const float* w_p0   = (const float*)d_in[1];
    const float* w_p1   = (const float*)d_in[2];
    const float* w_fc0  = (const float*)d_in[3];
    const float* b_fc0  = (const float*)d_in[4];
    const float* w_fc1  = (const float*)d_in[5];
    float* out = (float*)d_out;

    // step keys: jax.random.split(jax.random.key(42), 32) (partitionable)
    KeyArr keys;
    for (int j = 0; j < STEPS; ++j) {
        uint32_t a, b;
        threefry2x32(0u, 42u, 0u, (uint32_t)j, a, b);
        keys.k0[j] = a; keys.k1[j] = b;
    }

    cudaFuncSetAttribute(nca_step_kernel,
                         cudaFuncAttributeMaxDynamicSharedMemorySize, SMEM_BYTES);

    nca_pack_kernel<<<NPIX / 256, 256>>>(x);
    nca_maskall_kernel<<<NPIX / 256, 256>>>(keys);
    for (int s = 0; s < STEPS; ++s) {
        nca_step_kernel<<<TOT_BLOCKS, 128, SMEM_BYTES>>>(
            s & 1, s, w_p0, w_p1, w_fc0, b_fc0, w_fc1);
    }
    nca_unpack_kernel<<<NPIX / 256, 256>>>(out);
}

// round 5
// speedup vs baseline: 2.5861x; 1.0650x over previous
#include <cuda_runtime.h>
#include <cstdint>

// ---------------------------------------------------------------------------
// Problem constants
// ---------------------------------------------------------------------------
#define BATCH 8
#define IMG   256
#define CCH   16
#define HID   128
#define NPIX  (BATCH * IMG * IMG)          // 524288 pixels
#define STATE_ELEMS (NPIX * CCH)
#define STEPS 32
#define LIST_CAP (NPIX / 2 + 8192)

typedef unsigned long long u64;

__device__ float g_state[2][STATE_ELEMS];
__device__ int g_list[STEPS][LIST_CAP];
__device__ int g_ilist[STEPS][LIST_CAP];
__device__ int g_cnt[STEPS];
__device__ int g_icnt[STEPS];

struct KeyArr { uint32_t k0[STEPS]; uint32_t k1[STEPS]; };

// ---------------------------------------------------------------------------
// packed f32x2 helpers (bit-exact: two independent rn fp32 FMAs)
// ---------------------------------------------------------------------------
static __device__ __forceinline__ u64 pack2dup(float x) {
    u64 r; asm("mov.b64 %0, {%1, %1};" : "=l"(r) : "f"(x)); return r;
}
static __device__ __forceinline__ void ffma2(u64& acc, u64 a, u64 b) {
    asm("fma.rn.f32x2 %0, %1, %2, %0;" : "+l"(acc) : "l"(a), "l"(b));
}
static __device__ __forceinline__ float2 unpack2(u64 v) {
    float2 f; asm("mov.b64 {%0, %1}, %2;" : "=f"(f.x), "=f"(f.y) : "l"(v)); return f;
}

// ---------------------------------------------------------------------------
// Threefry-2x32 (20 rounds) — exact JAX implementation
// ---------------------------------------------------------------------------
static __host__ __device__ __forceinline__ uint32_t tf_rotl(uint32_t v, int r) {
    return (v << r) | (v >> (32 - r));
}
static __host__ __device__ __forceinline__ void threefry2x32(
    uint32_t k0, uint32_t k1, uint32_t x0, uint32_t x1,
    uint32_t& o0, uint32_t& o1)
{
    uint32_t ks2 = k0 ^ k1 ^ 0x1BD11BDAu;
    x0 += k0; x1 += k1;
    x0 += x1; x1 = tf_rotl(x1, 13); x1 ^= x0;
    x0 += x1; x1 = tf_rotl(x1, 15); x1 ^= x0;
    x0 += x1; x1 = tf_rotl(x1, 26); x1 ^= x0;
    x0 += x1; x1 = tf_rotl(x1,  6); x1 ^= x0;
    x0 += k1; x1 += ks2 + 1u;
    x0 += x1; x1 = tf_rotl(x1, 17); x1 ^= x0;
    x0 += x1; x1 = tf_rotl(x1, 29); x1 ^= x0;
    x0 += x1; x1 = tf_rotl(x1, 16); x1 ^= x0;
    x0 += x1; x1 = tf_rotl(x1, 24); x1 ^= x0;
    x0 += ks2; x1 += k0 + 2u;
    x0 += x1; x1 = tf_rotl(x1, 13); x1 ^= x0;
    x0 += x1; x1 = tf_rotl(x1, 15); x1 ^= x0;
    x0 += x1; x1 = tf_rotl(x1, 26); x1 ^= x0;
    x0 += x1; x1 = tf_rotl(x1,  6); x1 ^= x0;
    x0 += k0; x1 += k1 + 3u;
    x0 += x1; x1 = tf_rotl(x1, 17); x1 ^= x0;
    x0 += x1; x1 = tf_rotl(x1, 29); x1 ^= x0;
    x0 += x1; x1 = tf_rotl(x1, 16); x1 ^= x0;
    x0 += x1; x1 = tf_rotl(x1, 24); x1 ^= x0;
    x0 += k1; x1 += ks2 + 4u;
    x0 += x1; x1 = tf_rotl(x1, 13); x1 ^= x0;
    x0 += x1; x1 = tf_rotl(x1, 15); x1 ^= x0;
    x0 += x1; x1 = tf_rotl(x1, 26); x1 ^= x0;
    x0 += x1; x1 = tf_rotl(x1,  6); x1 ^= x0;
    x0 += ks2; x1 += k0 + 5u;
    o0 = x0; o1 = x1;
}

// ---------------------------------------------------------------------------
// Pack: NCHW -> NHWC state 0; zero list counters
// ---------------------------------------------------------------------------
__global__ void nca_pack_kernel(const float* __restrict__ x)
{
    int p = blockIdx.x * 256 + threadIdx.x;
    if (blockIdx.x == 0 && threadIdx.x < STEPS) {
        g_cnt[threadIdx.x] = 0;
        g_icnt[threadIdx.x] = 0;
    }
    if (p >= NPIX) return;
    int b  = p >> 16;
    int hw = p & 65535;
    float v[CCH];
#pragma unroll
    for (int c = 0; c < CCH; ++c)
        v[c] = x[((size_t)(b * CCH + c) << 16) + hw];
    float4* dst = reinterpret_cast<float4*>(g_state[0] + ((size_t)p << 4));
    dst[0] = make_float4(v[0],  v[1],  v[2],  v[3]);
    dst[1] = make_float4(v[4],  v[5],  v[6],  v[7]);
    dst[2] = make_float4(v[8],  v[9],  v[10], v[11]);
    dst[3] = make_float4(v[12], v[13], v[14], v[15]);
}

// ---------------------------------------------------------------------------
// All 32 fire masks in one pass
// ---------------------------------------------------------------------------
__global__ void nca_maskall_kernel(KeyArr keys)
{
    int p = blockIdx.x * 256 + threadIdx.x;
    const int lane = threadIdx.x & 31;

#pragma unroll 1
    for (int s = 0; s < STEPS; ++s) {
        uint32_t r0, r1;
        threefry2x32(keys.k0[s], keys.k1[s], 0u, (uint32_t)p, r0, r1);
        uint32_t bits = r0 ^ r1;
        float u = __uint_as_float((bits >> 9) | 0x3f800000u) - 1.0f;
        bool active = (u <= 0.5f);

        unsigned ball = __ballot_sync(0xffffffffu, active);
        int nact = __popc(ball);
        int rank = __popc(ball & ((1u << lane) - 1u));
        int baseA = 0, baseI = 0;
        if (lane == 0) {
            if (nact > 0)  baseA = atomicAdd(&g_cnt[s], nact);
            if (nact < 32) baseI = atomicAdd(&g_icnt[s], 32 - nact);
        }
        baseA = __shfl_sync(0xffffffffu, baseA, 0);
        baseI = __shfl_sync(0xffffffffu, baseI, 0);
        if (active) g_list[s][baseA + rank] = p;
        else        g_ilist[s][baseI + (lane - rank)] = p;
    }
}

// ---------------------------------------------------------------------------
// Per-step fused kernel: active MLP blocks + inactive copy blocks
// ---------------------------------------------------------------------------
#define SMEM_FLOATS (6144 + 2048 + 128 + 144 + 144)
#define SMEM_BYTES  (SMEM_FLOATS * 4)
#define UPD_BLOCKS  512
#define CPY_BLOCKS  256
#define TOT_BLOCKS  (UPD_BLOCKS + CPY_BLOCKS)

__global__ void __launch_bounds__(128)
nca_step_kernel(int src, int step,
                const float* __restrict__ w_p0, const float* __restrict__ w_p1,
                const float* __restrict__ w_fc0, const float* __restrict__ b_fc0,
                const float* __restrict__ w_fc1)
{
    const float* cur = g_state[src];
    float*       nxt = g_state[src ^ 1];
    const int tid = threadIdx.x;

    // ---------------- inactive copy-through blocks ----------------
    if (blockIdx.x >= UPD_BLOCKS) {
        const int icnt = g_icnt[step];
        const int* il = g_ilist[step];
        for (int i = (blockIdx.x - UPD_BLOCKS) * 128 + tid; i < icnt;
             i += CPY_BLOCKS * 128) {
            int p = il[i];
            const float4* s = reinterpret_cast<const float4*>(cur + ((size_t)p << 4));
            float4* d = reinterpret_cast<float4*>(nxt + ((size_t)p << 4));
            d[0] = s[0]; d[1] = s[1]; d[2] = s[2]; d[3] = s[3];
        }
        return;
    }

    // ---------------- active MLP blocks ----------------
    extern __shared__ float sm[];
    float* s_w0 = sm;            // 6144
    float* s_w1 = sm + 6144;     // 2048
    float* s_b  = sm + 8192;     // 128
    float* s_p0 = sm + 8320;     // 144
    float* s_p1 = sm + 8464;     // 144

    for (int i = tid; i < 6144; i += 128) s_w0[i] = w_fc0[i];
    for (int i = tid; i < 2048; i += 128) s_w1[i] = w_fc1[i];
    s_b[tid] = b_fc0[tid];
    for (int i = tid; i < 144; i += 128) { s_p0[i] = w_p0[i]; s_p1[i] = w_p1[i]; }
    __syncthreads();

    const int count = g_cnt[step];
    const int* al = g_list[step];

#pragma unroll 1
    for (int base = blockIdx.x * 256; base < count; base += UPD_BLOCKS * 256) {
        int iA = base + tid;
        if (iA >= count) continue;
        int iB = base + 128 + tid;
        int pA = al[iA];
        int pB = (iB < count) ? al[iB] : pA;   // duplicate is benign

        const float* baseA = cur + ((size_t)(pA >> 16) << 20);
        const float* baseB = cur + ((size_t)(pB >> 16) << 20);
        const int hA = (pA >> 8) & 255, wA = pA & 255;
        const int hB = (pB >> 8) & 255, wB = pB & 255;

        // ---- perception for BOTH pixels, tap-outer (shared tap weights) ----
        float percA[48], percB[48];
        {
            u64 cA0[8], cA1[8], cB0[8], cB1[8];
#pragma unroll
            for (int k = 0; k < 8; ++k) { cA0[k]=0ull; cA1[k]=0ull; cB0[k]=0ull; cB1[k]=0ull; }

#pragma unroll
            for (int dh = -1; dh <= 1; ++dh) {
                int hhA = hA + dh; hhA = (hhA < 0) ? 1 : ((hhA > 255) ? 254 : hhA);
                int hhB = hB + dh; hhB = (hhB < 0) ? 1 : ((hhB > 255) ? 254 : hhB);
#pragma unroll
                for (int dw = -1; dw <= 1; ++dw) {
                    int wwA = wA + dw; wwA = (wwA < 0) ? 1 : ((wwA > 255) ? 254 : wwA);
                    int wwB = wB + dw; wwB = (wwB < 0) ? 1 : ((wwB > 255) ? 254 : wwB);
                    const ulonglong2* pxA = reinterpret_cast<const ulonglong2*>(
                        baseA + (((size_t)((hhA << 8) | wwA)) << 4));
                    const ulonglong2* pxB = reinterpret_cast<const ulonglong2*>(
                        baseB + (((size_t)((hhB << 8) | wwB)) << 4));
                    ulonglong2 qa0 = pxA[0], qa1 = pxA[1], qa2 = pxA[2], qa3 = pxA[3];
                    ulonglong2 qb0 = pxB[0], qb1 = pxB[1], qb2 = pxB[2], qb3 = pxB[3];
                    u64 va[8] = {qa0.x,qa0.y,qa1.x,qa1.y,qa2.x,qa2.y,qa3.x,qa3.y};
                    u64 vb[8] = {qb0.x,qb0.y,qb1.x,qb1.y,qb2.x,qb2.y,qb3.x,qb3.y};
                    const int tap = (dh + 1) * 3 + (dw + 1);
                    const ulonglong2* wp0 = reinterpret_cast<const ulonglong2*>(s_p0 + tap * 16);
                    const ulonglong2* wp1 = reinterpret_cast<const ulonglong2*>(s_p1 + tap * 16);
#pragma unroll
                    for (int q = 0; q < 4; ++q) {
                        ulonglong2 t0 = wp0[q], t1 = wp1[q];
                        ffma2(cA0[2*q],   va[2*q],   t0.x);
                        ffma2(cA0[2*q+1], va[2*q+1], t0.y);
                        ffma2(cA1[2*q],   va[2*q],   t1.x);
                        ffma2(cA1[2*q+1], va[2*q+1], t1.y);
                        ffma2(cB0[2*q],   vb[2*q],   t0.x);
                        ffma2(cB0[2*q+1], vb[2*q+1], t0.y);
                        ffma2(cB1[2*q],   vb[2*q],   t1.x);
                        ffma2(cB1[2*q+1], vb[2*q+1], t1.y);
                    }
                    if (dh == 0 && dw == 0) {
#pragma unroll
                        for (int q = 0; q < 8; ++q) {
                            float2 fa = unpack2(va[q]);
                            float2 fb = unpack2(vb[q]);
                            percA[2*q] = fa.x; percA[2*q+1] = fa.y;
                            percB[2*q] = fb.x; percB[2*q+1] = fb.y;
                        }
                    }
                }
            }
#pragma unroll
            for (int k = 0; k < 8; ++k) {
                float2 a0 = unpack2(cA0[k]);
                float2 a1 = unpack2(cA1[k]);
                float2 b0 = unpack2(cB0[k]);
                float2 b1 = unpack2(cB1[k]);
                percA[16 + 2*k] = a0.x; percA[16 + 2*k + 1] = a0.y;
                percA[32 + 2*k] = a1.x; percA[32 + 2*k + 1] = a1.y;
                percB[16 + 2*k] = b0.x; percB[16 + 2*k + 1] = b0.y;
                percB[32 + 2*k] = b1.x; percB[32 + 2*k + 1] = b1.y;
            }
        }

        // ---- fused MLP: 8 chunks of 16 hidden units, 2 pixels ----
        u64 dxA[8], dxB[8];
#pragma unroll
        for (int k = 0; k < 8; ++k) { dxA[k] = 0ull; dxB[k] = 0ull; }

#pragma unroll 1
        for (int chunk = 0; chunk < 8; ++chunk) {
            u64 hA2[8], hB2[8];
            {
                const ulonglong2* bv = reinterpret_cast<const ulonglong2*>(s_b + chunk * 16);
#pragma unroll
                for (int q = 0; q < 4; ++q) {
                    ulonglong2 t = bv[q];
                    hA2[2*q] = t.x; hA2[2*q+1] = t.y;
                    hB2[2*q] = t.x; hB2[2*q+1] = t.y;
                }
            }
#pragma unroll
            for (int c = 0; c < 48; ++c) {
                u64 pa2 = pack2dup(percA[c]);
                u64 pb2 = pack2dup(percB[c]);
                const ulonglong2* wr = reinterpret_cast<const ulonglong2*>(
                    s_w0 + c * HID + chunk * 16);
#pragma unroll
                for (int q = 0; q < 4; ++q) {
                    ulonglong2 t = wr[q];
                    ffma2(hA2[2*q],   pa2, t.x);
                    ffma2(hA2[2*q+1], pa2, t.y);
                    ffma2(hB2[2*q],   pb2, t.x);
                    ffma2(hB2[2*q+1], pb2, t.y);
                }
            }
            // relu + second layer
#pragma unroll
            for (int jj = 0; jj < 4; ++jj) {
                float2 ha = unpack2(hA2[2*jj]);
                float2 ha2 = unpack2(hA2[2*jj+1]);
                float2 hb = unpack2(hB2[2*jj]);
                float2 hb2 = unpack2(hB2[2*jj+1]);
                int j0 = chunk * 16 + 4 * jj;
                const ulonglong2* w10 = reinterpret_cast<const ulonglong2*>(s_w1 + ((j0+0) << 4));
                const ulonglong2* w11 = reinterpret_cast<const ulonglong2*>(s_w1 + ((j0+1) << 4));
                const ulonglong2* w12 = reinterpret_cast<const ulonglong2*>(s_w1 + ((j0+2) << 4));
                const ulonglong2* w13 = reinterpret_cast<const ulonglong2*>(s_w1 + ((j0+3) << 4));
                u64 dA0 = pack2dup(fmaxf(ha.x,  0.f));
                u64 dA1 = pack2dup(fmaxf(ha.y,  0.f));
                u64 dA2 = pack2dup(fmaxf(ha2.x, 0.f));
                u64 dA3 = pack2dup(fmaxf(ha2.y, 0.f));
                u64 dB0 = pack2dup(fmaxf(hb.x,  0.f));
                u64 dB1 = pack2dup(fmaxf(hb.y,  0.f));
                u64 dB2 = pack2dup(fmaxf(hb2.x, 0.f));
                u64 dB3 = pack2dup(fmaxf(hb2.y, 0.f));
#pragma unroll
                for (int q = 0; q < 4; ++q) {
                    ulonglong2 t0 = w10[q];
                    ffma2(dxA[2*q],   dA0, t0.x);
                    ffma2(dxA[2*q+1], dA0, t0.y);
                    ffma2(dxB[2*q],   dB0, t0.x);
                    ffma2(dxB[2*q+1], dB0, t0.y);
                }
#pragma unroll
                for (int q = 0; q < 4; ++q) {
                    ulonglong2 t1 = w11[q];
                    ffma2(dxA[2*q],   dA1, t1.x);
                    ffma2(dxA[2*q+1], dA1, t1.y);
                    ffma2(dxB[2*q],   dB1, t1.x);
                    ffma2(dxB[2*q+1], dB1, t1.y);
                }
#pragma unroll
                for (int q = 0; q < 4; ++q) {
                    ulonglong2 t2 = w12[q];
                    ffma2(dxA[2*q],   dA2, t2.x);
                    ffma2(dxA[2*q+1], dA2, t2.y);
                    ffma2(dxB[2*q],   dB2, t2.x);
                    ffma2(dxB[2*q+1], dB2, t2.y);
                }
#pragma unroll
                for (int q = 0; q < 4; ++q) {
                    ulonglong2 t3 = w13[q];
                    ffma2(dxA[2*q],   dA3, t3.x);
                    ffma2(dxA[2*q+1], dA3, t3.y);
                    ffma2(dxB[2*q],   dB3, t3.x);
                    ffma2(dxB[2*q+1], dB3, t3.y);
                }
            }
        }

        // ---- residual update; channels 0..2 pinned ----
        float outA[CCH], outB[CCH];
#pragma unroll
        for (int k = 0; k < 8; ++k) {
            float2 da = unpack2(dxA[k]);
            float2 db = unpack2(dxB[k]);
            outA[2*k]   = percA[2*k]   + da.x;
            outA[2*k+1] = percA[2*k+1] + da.y;
            outB[2*k]   = percB[2*k]   + db.x;
            outB[2*k+1] = percB[2*k+1] + db.y;
        }
        outA[0] = percA[0]; outA[1] = percA[1]; outA[2] = percA[2];
        outB[0] = percB[0]; outB[1] = percB[1]; outB[2] = percB[2];

        float4* dA = reinterpret_cast<float4*>(nxt + ((size_t)pA << 4));
        dA[0] = make_float4(outA[0],  outA[1],  outA[2],  outA[3]);
        dA[1] = make_float4(outA[4],  outA[5],  outA[6],  outA[7]);
        dA[2] = make_float4(outA[8],  outA[9],  outA[10], outA[11]);
        dA[3] = make_float4(outA[12], outA[13], outA[14], outA[15]);
        float4* dB = reinterpret_cast<float4*>(nxt + ((size_t)pB << 4));
        dB[0] = make_float4(outB[0],  outB[1],  outB[2],  outB[3]);
        dB[1] = make_float4(outB[4],  outB[5],  outB[6],  outB[7]);
        dB[2] = make_float4(outB[8],  outB[9],  outB[10], outB[11]);
        dB[3] = make_float4(outB[12], outB[13], outB[14], outB[15]);
    }
}

// ---------------------------------------------------------------------------
// Unpack
// ---------------------------------------------------------------------------
__global__ void nca_unpack_kernel(float* __restrict__ out)
{
    int p = blockIdx.x * 256 + threadIdx.x;
    if (p >= NPIX) return;
    int b  = p >> 16;
    int hw = p & 65535;
    const float4* src = reinterpret_cast<const float4*>(g_state[0] + ((size_t)p << 4));
    float4 a0 = src[0], a1 = src[1], a2 = src[2], a3 = src[3];
    float v[CCH] = {a0.x,a0.y,a0.z,a0.w, a1.x,a1.y,a1.z,a1.w,
                    a2.x,a2.y,a2.z,a2.w, a3.x,a3.y,a3.z,a3.w};
    out[((size_t)b << 16) + hw] = v[3];
    float* xf = out + NPIX;
#pragma unroll
    for (int c = 0; c < CCH; ++c)
        xf[((size_t)(b * CCH + c) << 16) + hw] = v[c];
}

// ---------------------------------------------------------------------------
// Launch
// ---------------------------------------------------------------------------
extern "C" void kernel_launch(void* const* d_in, const int* in_sizes, int n_in,
                              void* d_out, int out_size)
{
    const float* x      = (const float*)d_in[0];
    const float* w_p0   = (const float*)d_in[1];
    const float* w_p1   = (const float*)d_in[2];
    const float* w_fc0  = (const float*)d_in[3];
    const float* b_fc0  = (const float*)d_in[4];
    const float* w_fc1  = (const float*)d_in[5];
    float* out = (float*)d_out;

    KeyArr keys;
    for (int j = 0; j < STEPS; ++j) {
        uint32_t a, b;
        threefry2x32(0u, 42u, 0u, (uint32_t)j, a, b);
        keys.k0[j] = a; keys.k1[j] = b;
    }

    cudaFuncSetAttribute(nca_step_kernel,
                         cudaFuncAttributeMaxDynamicSharedMemorySize, SMEM_BYTES);

    nca_pack_kernel<<<NPIX / 256, 256>>>(x);
    nca_maskall_kernel<<<NPIX / 256, 256>>>(keys);
    for (int s = 0; s < STEPS; ++s) {
        nca_step_kernel<<<TOT_BLOCKS, 128, SMEM_BYTES>>>(
            s & 1, s, w_p0, w_p1, w_fc0, b_fc0, w_fc1);
    }
    nca_unpack_kernel<<<NPIX / 256, 256>>>(out);
}